// round 12
// baseline (speedup 1.0000x reference)
#include <cuda_runtime.h>
#include <cuda_bf16.h>
#include <math.h>
#include <stdint.h>

#define BATCH 4
#define SEQ   4096
#define NROWS (BATCH * SEQ)
#define EMB   768
#define QD    64
#define CCOLS 192

// ---------------- scratch ----------------------------------------------------
__device__ float g_C[(size_t)NROWS * CCOLS];
__device__ __nv_bfloat16 g_Bh[(size_t)EMB * CCOLS];  // k-major: [k][n]
__device__ __nv_bfloat16 g_Bl[(size_t)EMB * CCOLS];
__device__ float g_Spart[256 * 64];                  // per-m-tile V col sums

// ---------------- PTX helpers ------------------------------------------------
__device__ __forceinline__ uint32_t smem_u32(const void* p) {
    uint32_t a;
    asm("{ .reg .u64 t; cvta.to.shared.u64 t, %1; cvt.u32.u64 %0, t; }"
        : "=r"(a) : "l"(p));
    return a;
}
#define LDM4(r, addr)                                                        \
    asm volatile("ldmatrix.sync.aligned.m8n8.x4.shared.b16 {%0,%1,%2,%3}, [%4];" \
                 : "=r"((r)[0]), "=r"((r)[1]), "=r"((r)[2]), "=r"((r)[3])    \
                 : "r"(addr))
#define LDMT4(r, addr)                                                       \
    asm volatile("ldmatrix.sync.aligned.m8n8.x4.trans.shared.b16 {%0,%1,%2,%3}, [%4];" \
                 : "=r"((r)[0]), "=r"((r)[1]), "=r"((r)[2]), "=r"((r)[3])    \
                 : "r"(addr))
#define MMA(d, a, b0, b1)                                                    \
    asm volatile(                                                            \
        "mma.sync.aligned.m16n8k16.row.col.f32.bf16.bf16.f32 "               \
        "{%0,%1,%2,%3}, {%4,%5,%6,%7}, {%8,%9}, {%0,%1,%2,%3};"              \
        : "+f"((d)[0]), "+f"((d)[1]), "+f"((d)[2]), "+f"((d)[3])             \
        : "r"((a)[0]), "r"((a)[1]), "r"((a)[2]), "r"((a)[3]),                \
          "r"(b0), "r"(b1))
#define CP16(dst, src)                                                       \
    asm volatile("cp.async.cg.shared.global [%0], [%1], 16;"                 \
                 :: "r"(dst), "l"(src))
#define CP_COMMIT() asm volatile("cp.async.commit_group;")
#define CP_WAIT1()  asm volatile("cp.async.wait_group 1;")
#define CP_WAIT0()  asm volatile("cp.async.wait_group 0;")

// ---------------- weight split (k-major), vectorized --------------------------
__global__ __launch_bounds__(256) void prep_w(
    const float* __restrict__ Wq, const float* __restrict__ Wk,
    const float* __restrict__ Wv)
{
    int q = blockIdx.x * 256 + threadIdx.x;      // over EMB*CCOLS/4 = 36864
    if (q >= EMB * CCOLS / 4) return;
    int n4 = (q % (CCOLS / 4)) * 4;
    int k  = q / (CCOLS / 4);
    const float* W = (n4 < 64) ? Wq : (n4 < 128) ? Wk : Wv;
    const float* src = W + (size_t)k * 64 + (n4 & 63);
    float4 v = *(const float4*)src;
    __nv_bfloat162 h01 = __floats2bfloat162_rn(v.x, v.y);
    __nv_bfloat162 h23 = __floats2bfloat162_rn(v.z, v.w);
    float l0 = v.x - __bfloat162float(h01.x);
    float l1 = v.y - __bfloat162float(h01.y);
    float l2 = v.z - __bfloat162float(h23.x);
    float l3 = v.w - __bfloat162float(h23.y);
    __nv_bfloat162 p01 = __floats2bfloat162_rn(l0, l1);
    __nv_bfloat162 p23 = __floats2bfloat162_rn(l2, l3);
    size_t o = (size_t)k * CCOLS + n4;
    *(uint2*)(g_Bh + o) = make_uint2(*(uint32_t*)&h01, *(uint32_t*)&h23);
    *(uint2*)(g_Bl + o) = make_uint2(*(uint32_t*)&p01, *(uint32_t*)&p23);
}

// ---------------- pipelined bf16-split HMMA GEMM, 2 CTAs/SM --------------------
// BM=64, BN=96 (nh = blockIdx.y selects N-half), BK=64. 128 threads = 4 warps
// as 2(m) x 2(n); warp tile 32x48. Smem ~90KB -> 2 CTAs resident per SM.
#define SA_BYTES (64 * 144)                  // 9216 per (stage,hl)
#define SB_BYTES (64 * 208)                  // 13312 per (stage,hl)
#define SA_OFF(s, h) (((s) * 2 + (h)) * SA_BYTES)
#define SB_OFF(s, h) (4 * SA_BYTES + ((s) * 2 + (h)) * SB_BYTES)
#define SM_TOTAL (4 * SA_BYTES + 4 * SB_BYTES)   // 90112

__global__ __launch_bounds__(128, 2)
void mma_gemm(const float* __restrict__ x,
              const float* __restrict__ bq, const float* __restrict__ bk,
              const float* __restrict__ bv)
{
    extern __shared__ char smem[];
    __shared__ float sbias[96];
    __shared__ float smemV[2][64];

    const uint32_t sb = smem_u32(smem);
    const int tid = threadIdx.x;
    const int wid = tid >> 5, lane = tid & 31;
    const int wm = wid & 1, wn = wid >> 1;
    const int rowTile = blockIdx.x * 64;
    const int nh = blockIdx.y;               // 0: cols 0..95, 1: cols 96..191

    if (tid < 96) {
        int gc = nh * 96 + tid;
        sbias[tid] = (gc < 64) ? bq[gc] : (gc < 128) ? bk[gc - 64]
                                                     : bv[gc - 128];
    }

    float acc[2][6][4];
#pragma unroll
    for (int i = 0; i < 2; i++)
#pragma unroll
        for (int j = 0; j < 6; j++)
#pragma unroll
            for (int l = 0; l < 4; l++) acc[i][j][l] = 0.f;

    const int g = lane >> 3, r = lane & 7;
    const int a_off = (r + ((g & 1) ? 8 : 0)) * 144 + (((g >= 2) ? 8 : 0) * 2);
    const int b_off = ((g & 1) * 8 + r) * 208 + (((g >= 2) ? 8 : 0) * 2);

    uint32_t aAh[2], aAl[2], aBh[2], aBl[2];
#pragma unroll
    for (int s = 0; s < 2; s++) {
        aAh[s] = sb + SA_OFF(s, 0) + wm * 32 * 144 + a_off;
        aAl[s] = sb + SA_OFF(s, 1) + wm * 32 * 144 + a_off;
        aBh[s] = sb + SB_OFF(s, 0) + wn * 48 * 2 + b_off;
        aBl[s] = sb + SB_OFF(s, 1) + wn * 48 * 2 + b_off;
    }

    // raw A fp32 in registers, one chunk ahead; converted at STS time
    float4 Av[8];

#define LDG_A_RAW(ch)                                                        \
    do {                                                                     \
        const int k0_ = (ch) * 64;                                           \
        _Pragma("unroll")                                                    \
        for (int i = 0; i < 8; i++) {                                        \
            int idx = tid + i * 128;                                         \
            int rr = idx >> 4, c4 = idx & 15;                                \
            Av[i] = *(const float4*)(x + (size_t)(rowTile + rr) * EMB +      \
                                     k0_ + c4 * 4);                          \
        }                                                                    \
    } while (0)

#define STS_A_CONV(ch)                                                       \
    do {                                                                     \
        const int s_ = (ch) & 1;                                             \
        _Pragma("unroll")                                                    \
        for (int i = 0; i < 8; i++) {                                        \
            int idx = tid + i * 128;                                         \
            int rr = idx >> 4, c4 = idx & 15;                                \
            float4 v = Av[i];                                                \
            __nv_bfloat162 h01 = __floats2bfloat162_rn(v.x, v.y);            \
            __nv_bfloat162 h23 = __floats2bfloat162_rn(v.z, v.w);            \
            float l0 = v.x - __bfloat162float(h01.x);                        \
            float l1 = v.y - __bfloat162float(h01.y);                        \
            float l2 = v.z - __bfloat162float(h23.x);                        \
            float l3 = v.w - __bfloat162float(h23.y);                        \
            __nv_bfloat162 p01 = __floats2bfloat162_rn(l0, l1);              \
            __nv_bfloat162 p23 = __floats2bfloat162_rn(l2, l3);              \
            *(uint2*)(smem + SA_OFF(s_, 0) + rr * 144 + c4 * 8) =            \
                make_uint2(*(uint32_t*)&h01, *(uint32_t*)&h23);              \
            *(uint2*)(smem + SA_OFF(s_, 1) + rr * 144 + c4 * 8) =            \
                make_uint2(*(uint32_t*)&p01, *(uint32_t*)&p23);              \
        }                                                                    \
    } while (0)

#define LDG_B(ch)                                                            \
    do {                                                                     \
        const int s_ = (ch) & 1;                                             \
        const int k0_ = (ch) * 64;                                           \
        _Pragma("unroll")                                                    \
        for (int i = 0; i < 6; i++) {                                        \
            int j = tid + i * 128;            /* 0..767 */                   \
            int row = j / 12, c = j % 12;                                    \
            uint32_t dh = sb + SB_OFF(s_, 0) + row * 208 + c * 16;           \
            uint32_t dl = sb + SB_OFF(s_, 1) + row * 208 + c * 16;           \
            CP16(dh, g_Bh + (size_t)(k0_ + row) * CCOLS + nh * 96 + c * 8);  \
            CP16(dl, g_Bl + (size_t)(k0_ + row) * CCOLS + nh * 96 + c * 8);  \
        }                                                                    \
    } while (0)

    // ---- prologue ----
    LDG_B(0); CP_COMMIT();
    LDG_A_RAW(0);
    STS_A_CONV(0);
    LDG_B(1); CP_COMMIT();
    LDG_A_RAW(1);

    // ---- main loop ----
    for (int ch = 0; ch < 12; ch++) {
        const int s = ch & 1;
        if (ch < 11) CP_WAIT1(); else CP_WAIT0();
        __syncthreads();

#pragma unroll
        for (int ks = 0; ks < 4; ks++) {
            uint32_t ah[2][4], al[2][4];
            LDM4(ah[0], aAh[s] + ks * 32);
            LDM4(ah[1], aAh[s] + 16 * 144 + ks * 32);
            LDM4(al[0], aAl[s] + ks * 32);
            LDM4(al[1], aAl[s] + 16 * 144 + ks * 32);
#pragma unroll
            for (int nt = 0; nt < 3; nt++) {
                uint32_t bh[4], bl[4];
                LDMT4(bh, aBh[s] + ks * 3328 + nt * 32);
                LDMT4(bl, aBl[s] + ks * 3328 + nt * 32);
#pragma unroll
                for (int mt = 0; mt < 2; mt++) {
                    MMA(acc[mt][2 * nt],     ah[mt], bh[0], bh[1]);
                    MMA(acc[mt][2 * nt],     ah[mt], bl[0], bl[1]);
                    MMA(acc[mt][2 * nt],     al[mt], bh[0], bh[1]);
                    MMA(acc[mt][2 * nt + 1], ah[mt], bh[2], bh[3]);
                    MMA(acc[mt][2 * nt + 1], ah[mt], bl[2], bl[3]);
                    MMA(acc[mt][2 * nt + 1], al[mt], bh[2], bh[3]);
                }
            }
            if (ks == 0 && ch < 11)
                STS_A_CONV(ch + 1);   // writes A[s^1] only — safe
        }
        if (ch < 10) {
            __syncthreads();          // all reads of B[s] complete
            LDG_B(ch + 2); CP_COMMIT();
            LDG_A_RAW(ch + 2);
        }
    }

    // ---- epilogue: acc + bias -> g_C ----
    const int rbase = rowTile + wm * 32 + (lane >> 2);
#pragma unroll
    for (int mt = 0; mt < 2; mt++)
#pragma unroll
        for (int nt = 0; nt < 6; nt++) {
            int cl = wn * 48 + nt * 8 + 2 * (lane & 3);
            float b0 = sbias[cl], b1 = sbias[cl + 1];
            int col = nh * 96 + cl;
            int row = rbase + mt * 16;
            *(float2*)&g_C[(size_t)row * CCOLS + col] =
                make_float2(acc[mt][nt][0] + b0, acc[mt][nt][1] + b1);
            *(float2*)&g_C[(size_t)(row + 8) * CCOLS + col] =
                make_float2(acc[mt][nt][2] + b0, acc[mt][nt][3] + b1);
        }

    // ---- per-m-tile V column sums (nh==1 only; V = global cols 128..191) ----
    if (nh == 1) {
#pragma unroll
        for (int nt = 0; nt < 6; nt++) {
            int gcol0 = 96 + wn * 48 + nt * 8;
            if (gcol0 >= 128) {
                float s0 = acc[0][nt][0] + acc[0][nt][2] + acc[1][nt][0] + acc[1][nt][2];
                float s1 = acc[0][nt][1] + acc[0][nt][3] + acc[1][nt][1] + acc[1][nt][3];
#pragma unroll
                for (int m = 4; m <= 16; m <<= 1) {
                    s0 += __shfl_xor_sync(0xffffffffu, s0, m);
                    s1 += __shfl_xor_sync(0xffffffffu, s1, m);
                }
                if (lane < 4) {
                    int d = gcol0 - 128 + 2 * lane;
                    smemV[wm][d] = s0;
                    smemV[wm][d + 1] = s1;
                }
            }
        }
        __syncthreads();
        if (tid < 64)
            g_Spart[blockIdx.x * 64 + tid] =
                smemV[0][tid] + smemV[1][tid] + 64.f * sbias[32 + tid];
    }
}

// ---------------- epilogue: one warp per row; S reduced in-block ---------------
__global__ __launch_bounds__(256) void attn_epilogue(float* __restrict__ out)
{
    __shared__ float sS[64];
    const int lane = threadIdx.x;
    const int row = blockIdx.x * 8 + threadIdx.y;
    const int loc = row & (SEQ - 1);
    const int b = row >> 12;

    const int t = threadIdx.y * 32 + threadIdx.x;
    if (t < 64) {
        float s = 0.f;
#pragma unroll
        for (int c = 0; c < 64; c++)
            s += g_Spart[(b * 64 + c) * 64 + t];
#pragma unroll
        for (int j = 0; j < 3; j++)
            s -= g_C[(size_t)(b * SEQ + j) * CCOLS + 128 + t];
        sS[t] = s;
    }

    const float* Crow = g_C + (size_t)row * CCOLS;
    float2 q = *(const float2*)(Crow + lane * 2);
    const float* Kc = Crow + 64;

    float2 k1 = *(const float2*)(Kc + lane * 2);
    float d1 = q.x * k1.x + q.y * k1.y;
    float d0 = 0.f, d2 = 0.f;
    if (loc > 0) {
        float2 k0 = *(const float2*)(Kc - CCOLS + lane * 2);
        d0 = q.x * k0.x + q.y * k0.y;
    }
    if (loc < SEQ - 1) {
        float2 k2 = *(const float2*)(Kc + CCOLS + lane * 2);
        d2 = q.x * k2.x + q.y * k2.y;
    }
#pragma unroll
    for (int off = 16; off; off >>= 1) {
        d0 += __shfl_xor_sync(0xffffffffu, d0, off);
        d1 += __shfl_xor_sync(0xffffffffu, d1, off);
        d2 += __shfl_xor_sync(0xffffffffu, d2, off);
    }
    float e0 = (loc > 0) ? __expf(d0) : 1.f;
    float e1 = __expf(d1);
    float e2 = (loc < SEQ - 1) ? __expf(d2) : 1.f;
    float rZ = __fdividef(1.f, e0 + e1 + e2 + (float)(SEQ - 3));

    const float* Vb = g_C + (size_t)(b * SEQ) * CCOLS + 128;
    float2 v0 = *(const float2*)(Vb + lane * 2);
    float2 v1 = *(const float2*)(Vb + CCOLS + lane * 2);
    float2 v2 = *(const float2*)(Vb + 2 * CCOLS + lane * 2);

    __syncthreads();
    float2 s = *(const float2*)(sS + lane * 2);

    float2 o;
    o.x = (e0 * v0.x + e1 * v1.x + e2 * v2.x + s.x) * rZ;
    o.y = (e0 * v0.y + e1 * v1.y + e2 * v2.y + s.y) * rZ;
    *(float2*)(out + (size_t)row * QD + lane * 2) = o;
}

// ---------------- launch -------------------------------------------------------
extern "C" void kernel_launch(void* const* d_in, const int* in_sizes, int n_in,
                              void* d_out, int out_size)
{
    const float* x  = (const float*)d_in[0];
    const float* Wq = (const float*)d_in[1];
    const float* bq = (const float*)d_in[2];
    const float* Wk = (const float*)d_in[3];
    const float* bk = (const float*)d_in[4];
    const float* Wv = (const float*)d_in[5];
    const float* bv = (const float*)d_in[6];
    float* out = (float*)d_out;

    cudaFuncSetAttribute(mma_gemm, cudaFuncAttributeMaxDynamicSharedMemorySize,
                         SM_TOTAL);

    prep_w<<<(EMB * CCOLS / 4 + 255) / 256, 256>>>(Wq, Wk, Wv);
    mma_gemm<<<dim3(NROWS / 64, 2), 128, SM_TOTAL>>>(x, bq, bk, bv);
    attn_epilogue<<<NROWS / 8, dim3(32, 8)>>>(out);
}

// round 13
// speedup vs baseline: 1.2081x; 1.2081x over previous
#include <cuda_runtime.h>
#include <cuda_bf16.h>
#include <math.h>
#include <stdint.h>

#define BATCH 4
#define SEQ   4096
#define NROWS (BATCH * SEQ)
#define EMB   768
#define QD    64
#define CCOLS 192

// ---------------- scratch ----------------------------------------------------
__device__ float g_C[(size_t)NROWS * CCOLS];
__device__ __nv_bfloat16 g_Bh[(size_t)EMB * CCOLS];  // k-major: [k][n]
__device__ __nv_bfloat16 g_Bl[(size_t)EMB * CCOLS];
__device__ float g_Spart[128 * 64];                  // per-CTA V col sums
__device__ float g_S[BATCH * QD];

// ---------------- PTX helpers ------------------------------------------------
__device__ __forceinline__ uint32_t smem_u32(const void* p) {
    uint32_t a;
    asm("{ .reg .u64 t; cvta.to.shared.u64 t, %1; cvt.u32.u64 %0, t; }"
        : "=r"(a) : "l"(p));
    return a;
}
#define LDM4(r, addr)                                                        \
    asm volatile("ldmatrix.sync.aligned.m8n8.x4.shared.b16 {%0,%1,%2,%3}, [%4];" \
                 : "=r"((r)[0]), "=r"((r)[1]), "=r"((r)[2]), "=r"((r)[3])    \
                 : "r"(addr))
#define LDMT4(r, addr)                                                       \
    asm volatile("ldmatrix.sync.aligned.m8n8.x4.trans.shared.b16 {%0,%1,%2,%3}, [%4];" \
                 : "=r"((r)[0]), "=r"((r)[1]), "=r"((r)[2]), "=r"((r)[3])    \
                 : "r"(addr))
#define MMA(d, a, b0, b1)                                                    \
    asm volatile(                                                            \
        "mma.sync.aligned.m16n8k16.row.col.f32.bf16.bf16.f32 "               \
        "{%0,%1,%2,%3}, {%4,%5,%6,%7}, {%8,%9}, {%0,%1,%2,%3};"              \
        : "+f"((d)[0]), "+f"((d)[1]), "+f"((d)[2]), "+f"((d)[3])             \
        : "r"((a)[0]), "r"((a)[1]), "r"((a)[2]), "r"((a)[3]),                \
          "r"(b0), "r"(b1))
#define CP16(dst, src)                                                       \
    asm volatile("cp.async.cg.shared.global [%0], [%1], 16;"                 \
                 :: "r"(dst), "l"(src))
#define CP_COMMIT() asm volatile("cp.async.commit_group;")
#define CP_WAIT1()  asm volatile("cp.async.wait_group 1;")
#define CP_WAIT0()  asm volatile("cp.async.wait_group 0;")

// ---------------- weight split (k-major), 2 elems/thread ----------------------
__global__ __launch_bounds__(256) void prep_w(
    const float* __restrict__ Wq, const float* __restrict__ Wk,
    const float* __restrict__ Wv)
{
    int q = blockIdx.x * 256 + threadIdx.x;      // over EMB*CCOLS/2 = 73728
    if (q >= EMB * CCOLS / 2) return;
    int n2 = (q % (CCOLS / 2)) * 2;
    int k  = q / (CCOLS / 2);
    const float* W = (n2 < 64) ? Wq : (n2 < 128) ? Wk : Wv;
    const float* src = W + (size_t)k * 64 + (n2 & 63);
    float2 v = *(const float2*)src;
    __nv_bfloat162 h01 = __floats2bfloat162_rn(v.x, v.y);
    float l0 = v.x - __bfloat162float(h01.x);
    float l1 = v.y - __bfloat162float(h01.y);
    __nv_bfloat162 p01 = __floats2bfloat162_rn(l0, l1);
    size_t o = (size_t)k * CCOLS + n2;
    *(uint32_t*)(g_Bh + o) = *(uint32_t*)&h01;
    *(uint32_t*)(g_Bl + o) = *(uint32_t*)&p01;
}

// ---------------- pipelined bf16-split HMMA GEMM (R11 config) ------------------
#define SA_BYTES (128 * 144)
#define SB_BYTES (64 * 400)
#define SA_OFF(s, h) (((s) * 2 + (h)) * SA_BYTES)
#define SB_OFF(s, h) (4 * SA_BYTES + ((s) * 2 + (h)) * SB_BYTES)
#define SM_TOTAL (4 * SA_BYTES + 4 * SB_BYTES)   // 176128

__global__ __launch_bounds__(256, 1)
void mma_gemm(const float* __restrict__ x,
              const float* __restrict__ bq, const float* __restrict__ bk,
              const float* __restrict__ bv)
{
    extern __shared__ char smem[];
    __shared__ float sbias[CCOLS];
    __shared__ float smemV[4][64];

    const uint32_t sb = smem_u32(smem);
    const int tid = threadIdx.x;
    const int wid = tid >> 5, lane = tid & 31;
    const int wm = wid & 3, wn = wid >> 2;
    const int rowTile = blockIdx.x * 128;

    if (tid < CCOLS)
        sbias[tid] = (tid < 64) ? bq[tid] : (tid < 128) ? bk[tid - 64]
                                                        : bv[tid - 128];

    float acc[2][12][4];
#pragma unroll
    for (int i = 0; i < 2; i++)
#pragma unroll
        for (int j = 0; j < 12; j++)
#pragma unroll
            for (int l = 0; l < 4; l++) acc[i][j][l] = 0.f;

    const int g = lane >> 3, r = lane & 7;
    const int a_off = (r + ((g & 1) ? 8 : 0)) * 144 + (((g >= 2) ? 8 : 0) * 2);
    const int b_off = ((g & 1) * 8 + r) * 400 + (((g >= 2) ? 8 : 0) * 2);

    uint32_t aAh[2], aAl[2], aBh[2], aBl[2];
#pragma unroll
    for (int s = 0; s < 2; s++) {
        aAh[s] = sb + SA_OFF(s, 0) + wm * 32 * 144 + a_off;
        aAl[s] = sb + SA_OFF(s, 1) + wm * 32 * 144 + a_off;
        aBh[s] = sb + SB_OFF(s, 0) + wn * 96 * 2 + b_off;
        aBl[s] = sb + SB_OFF(s, 1) + wn * 96 * 2 + b_off;
    }

    // raw A fp32 in registers, one chunk ahead; converted at STS time
    float4 Av[8];

#define LDG_A_RAW(ch)                                                        \
    do {                                                                     \
        const int k0_ = (ch) * 64;                                           \
        _Pragma("unroll")                                                    \
        for (int i = 0; i < 8; i++) {                                        \
            int idx = tid + i * 256;                                         \
            int rr = idx >> 4, c4 = idx & 15;                                \
            Av[i] = *(const float4*)(x + (size_t)(rowTile + rr) * EMB +      \
                                     k0_ + c4 * 4);                          \
        }                                                                    \
    } while (0)

#define STS_A_CONV(ch)                                                       \
    do {                                                                     \
        const int s_ = (ch) & 1;                                             \
        _Pragma("unroll")                                                    \
        for (int i = 0; i < 8; i++) {                                        \
            int idx = tid + i * 256;                                         \
            int rr = idx >> 4, c4 = idx & 15;                                \
            float4 v = Av[i];                                                \
            __nv_bfloat162 h01 = __floats2bfloat162_rn(v.x, v.y);            \
            __nv_bfloat162 h23 = __floats2bfloat162_rn(v.z, v.w);            \
            float l0 = v.x - __bfloat162float(h01.x);                        \
            float l1 = v.y - __bfloat162float(h01.y);                        \
            float l2 = v.z - __bfloat162float(h23.x);                        \
            float l3 = v.w - __bfloat162float(h23.y);                        \
            __nv_bfloat162 p01 = __floats2bfloat162_rn(l0, l1);              \
            __nv_bfloat162 p23 = __floats2bfloat162_rn(l2, l3);              \
            *(uint2*)(smem + SA_OFF(s_, 0) + rr * 144 + c4 * 8) =            \
                make_uint2(*(uint32_t*)&h01, *(uint32_t*)&h23);              \
            *(uint2*)(smem + SA_OFF(s_, 1) + rr * 144 + c4 * 8) =            \
                make_uint2(*(uint32_t*)&p01, *(uint32_t*)&p23);              \
        }                                                                    \
    } while (0)

#define LDG_B(ch)                                                            \
    do {                                                                     \
        const int s_ = (ch) & 1;                                             \
        const int k0_ = (ch) * 64;                                           \
        _Pragma("unroll")                                                    \
        for (int i = 0; i < 6; i++) {                                        \
            int j = tid + i * 256;                                           \
            int row = j / 24, c = j % 24;                                    \
            uint32_t dh = sb + SB_OFF(s_, 0) + row * 400 + c * 16;           \
            uint32_t dl = sb + SB_OFF(s_, 1) + row * 400 + c * 16;           \
            CP16(dh, g_Bh + (size_t)(k0_ + row) * CCOLS + c * 8);            \
            CP16(dl, g_Bl + (size_t)(k0_ + row) * CCOLS + c * 8);            \
        }                                                                    \
    } while (0)

    // ---- prologue ----
    LDG_B(0); CP_COMMIT();
    LDG_A_RAW(0);
    STS_A_CONV(0);
    LDG_B(1); CP_COMMIT();
    LDG_A_RAW(1);

    // ---- main loop ----
    for (int ch = 0; ch < 12; ch++) {
        const int s = ch & 1;
        if (ch < 11) CP_WAIT1(); else CP_WAIT0();
        __syncthreads();

#pragma unroll
        for (int ks = 0; ks < 4; ks++) {
            uint32_t ah[2][4], al[2][4];
            LDM4(ah[0], aAh[s] + ks * 32);
            LDM4(ah[1], aAh[s] + 16 * 144 + ks * 32);
            LDM4(al[0], aAl[s] + ks * 32);
            LDM4(al[1], aAl[s] + 16 * 144 + ks * 32);

            uint32_t bh[2][4], bl[2][4];
            LDMT4(bh[0], aBh[s] + ks * 6400);
            LDMT4(bl[0], aBl[s] + ks * 6400);
#pragma unroll
            for (int nt = 0; nt < 6; nt++) {
                const int cur = nt & 1, nxt = cur ^ 1;
                if (nt < 5) {
                    LDMT4(bh[nxt], aBh[s] + ks * 6400 + (nt + 1) * 32);
                    LDMT4(bl[nxt], aBl[s] + ks * 6400 + (nt + 1) * 32);
                }
#pragma unroll
                for (int mt = 0; mt < 2; mt++) {
                    MMA(acc[mt][2 * nt],     ah[mt], bh[cur][0], bh[cur][1]);
                    MMA(acc[mt][2 * nt],     ah[mt], bl[cur][0], bl[cur][1]);
                    MMA(acc[mt][2 * nt],     al[mt], bh[cur][0], bh[cur][1]);
                    MMA(acc[mt][2 * nt + 1], ah[mt], bh[cur][2], bh[cur][3]);
                    MMA(acc[mt][2 * nt + 1], ah[mt], bl[cur][2], bl[cur][3]);
                    MMA(acc[mt][2 * nt + 1], al[mt], bh[cur][2], bh[cur][3]);
                }
            }
            if (ks == 0 && ch < 11)
                STS_A_CONV(ch + 1);   // A[s^1] only — safe
        }
        if (ch < 10) {
            __syncthreads();          // all reads of B[s] complete
            LDG_B(ch + 2); CP_COMMIT();
            LDG_A_RAW(ch + 2);
        }
    }

    // ---- epilogue: acc + bias -> g_C ----
    const int rbase = rowTile + wm * 32 + (lane >> 2);
#pragma unroll
    for (int mt = 0; mt < 2; mt++)
#pragma unroll
        for (int nt = 0; nt < 12; nt++) {
            int col = wn * 96 + nt * 8 + 2 * (lane & 3);
            float b0 = sbias[col], b1 = sbias[col + 1];
            int row = rbase + mt * 16;
            *(float2*)&g_C[(size_t)row * CCOLS + col] =
                make_float2(acc[mt][nt][0] + b0, acc[mt][nt][1] + b1);
            *(float2*)&g_C[(size_t)(row + 8) * CCOLS + col] =
                make_float2(acc[mt][nt][2] + b0, acc[mt][nt][3] + b1);
        }

    // ---- per-CTA V column sums ----
    if (wn == 1) {
#pragma unroll
        for (int nt = 4; nt < 12; nt++) {
            float s0 = acc[0][nt][0] + acc[0][nt][2] + acc[1][nt][0] + acc[1][nt][2];
            float s1 = acc[0][nt][1] + acc[0][nt][3] + acc[1][nt][1] + acc[1][nt][3];
#pragma unroll
            for (int m = 4; m <= 16; m <<= 1) {
                s0 += __shfl_xor_sync(0xffffffffu, s0, m);
                s1 += __shfl_xor_sync(0xffffffffu, s1, m);
            }
            if (lane < 4) {
                int d = (nt - 4) * 8 + 2 * lane;
                smemV[wm][d] = s0;
                smemV[wm][d + 1] = s1;
            }
        }
    }
    __syncthreads();
    if (tid < 64)
        g_Spart[blockIdx.x * 64 + tid] =
            smemV[0][tid] + smemV[1][tid] + smemV[2][tid] + smemV[3][tid] +
            128.f * sbias[128 + tid];
}

// ---------------- parallel final V-sum: 4 blocks, two-stage --------------------
__global__ __launch_bounds__(256) void sum_v_final()
{
    __shared__ float sm[4][64];
    const int b = blockIdx.x;
    const int d = threadIdx.x & 63;
    const int grp = threadIdx.x >> 6;      // 0..3, 8 chunks each
    float s = 0.f;
#pragma unroll
    for (int c = 0; c < 8; c++)
        s += g_Spart[(b * 32 + grp * 8 + c) * 64 + d];
    sm[grp][d] = s;
    __syncthreads();
    if (grp == 0) {
        float t = sm[0][d] + sm[1][d] + sm[2][d] + sm[3][d];
#pragma unroll
        for (int j = 0; j < 3; j++)
            t -= g_C[(size_t)(b * SEQ + j) * CCOLS + 128 + d];
        g_S[b * 64 + d] = t;
    }
}

// ---------------- epilogue: one warp per row, reads g_S directly ---------------
__global__ __launch_bounds__(256) void attn_epilogue(float* __restrict__ out)
{
    const int lane = threadIdx.x;
    const int row = blockIdx.x * 8 + threadIdx.y;
    const int loc = row & (SEQ - 1);
    const int b = row >> 12;

    const float* Crow = g_C + (size_t)row * CCOLS;
    float2 q = *(const float2*)(Crow + lane * 2);
    const float* Kc = Crow + 64;

    float2 k1 = *(const float2*)(Kc + lane * 2);
    float d1 = q.x * k1.x + q.y * k1.y;
    float d0 = 0.f, d2 = 0.f;
    if (loc > 0) {
        float2 k0 = *(const float2*)(Kc - CCOLS + lane * 2);
        d0 = q.x * k0.x + q.y * k0.y;
    }
    if (loc < SEQ - 1) {
        float2 k2 = *(const float2*)(Kc + CCOLS + lane * 2);
        d2 = q.x * k2.x + q.y * k2.y;
    }
#pragma unroll
    for (int off = 16; off; off >>= 1) {
        d0 += __shfl_xor_sync(0xffffffffu, d0, off);
        d1 += __shfl_xor_sync(0xffffffffu, d1, off);
        d2 += __shfl_xor_sync(0xffffffffu, d2, off);
    }
    float e0 = (loc > 0) ? __expf(d0) : 1.f;
    float e1 = __expf(d1);
    float e2 = (loc < SEQ - 1) ? __expf(d2) : 1.f;
    float rZ = __fdividef(1.f, e0 + e1 + e2 + (float)(SEQ - 3));

    const float* Vb = g_C + (size_t)(b * SEQ) * CCOLS + 128;
    float2 v0 = *(const float2*)(Vb + lane * 2);
    float2 v1 = *(const float2*)(Vb + CCOLS + lane * 2);
    float2 v2 = *(const float2*)(Vb + 2 * CCOLS + lane * 2);
    float2 s = *(const float2*)(g_S + b * 64 + lane * 2);

    float2 o;
    o.x = (e0 * v0.x + e1 * v1.x + e2 * v2.x + s.x) * rZ;
    o.y = (e0 * v0.y + e1 * v1.y + e2 * v2.y + s.y) * rZ;
    *(float2*)(out + (size_t)row * QD + lane * 2) = o;
}

// ---------------- launch -------------------------------------------------------
extern "C" void kernel_launch(void* const* d_in, const int* in_sizes, int n_in,
                              void* d_out, int out_size)
{
    const float* x  = (const float*)d_in[0];
    const float* Wq = (const float*)d_in[1];
    const float* bq = (const float*)d_in[2];
    const float* Wk = (const float*)d_in[3];
    const float* bk = (const float*)d_in[4];
    const float* Wv = (const float*)d_in[5];
    const float* bv = (const float*)d_in[6];
    float* out = (float*)d_out;

    cudaFuncSetAttribute(mma_gemm, cudaFuncAttributeMaxDynamicSharedMemorySize,
                         SM_TOTAL);

    prep_w<<<(EMB * CCOLS / 2 + 255) / 256, 256>>>(Wq, Wk, Wv);
    mma_gemm<<<NROWS / 128, 256, SM_TOTAL>>>(x, bq, bk, bv);
    sum_v_final<<<BATCH, 256>>>();
    attn_epilogue<<<NROWS / 8, dim3(32, 8)>>>(out);
}